// round 1
// baseline (speedup 1.0000x reference)
#include <cuda_runtime.h>

#define NND 32768
#define NE  491520
#define FIN 11
#define HD  64
#define NG  2048
#define NPG 16
#define NR  1024
#define NL  4
#define EINC 129
#define NINC 139

// ---------------- scratch (device globals; no allocation) ----------------
__device__ float g_h[NND * HD];
__device__ float g_h2[NND * HD];
__device__ float g_PA[NND * HD];
__device__ float g_PB[NND * HD];
__device__ float g_agg[NND * HD];
__device__ float g_radial[NE];

__device__ __forceinline__ float silu(float x) {
    return x / (1.0f + __expf(-x));
}

// ---------------- embedding: h = h0 @ emb_w + emb_b ----------------
__global__ void k_embed(const float* __restrict__ h0,
                        const float* __restrict__ emb_w,
                        const float* __restrict__ emb_b) {
    int idx = blockIdx.x * blockDim.x + threadIdx.x;   // over N*H
    int n = idx >> 6, j = idx & 63;
    float acc = emb_b[j];
#pragma unroll
    for (int f = 0; f < FIN; f++)
        acc += h0[n * FIN + f] * emb_w[f * HD + j];
    g_h[idx] = acc;
}

// ---------------- radial per edge ----------------
__global__ void k_radial(const int* __restrict__ edges,
                         const float* __restrict__ pos) {
    int e = blockIdx.x * blockDim.x + threadIdx.x;
    if (e >= NE) return;
    int r = edges[e], c = edges[NE + e];
    float dx = pos[r * 3 + 0] - pos[c * 3 + 0];
    float dy = pos[r * 3 + 1] - pos[c * 3 + 1];
    float dz = pos[r * 3 + 2] - pos[c * 3 + 2];
    g_radial[e] = dx * dx + dy * dy + dz * dz;
}

// ---------------- per-layer precompute: PA = h@W1a + b1, PB = h@W1b; zero agg ----------------
__global__ void k_precomp(const float* __restrict__ h,
                          const float* __restrict__ W1,
                          const float* __restrict__ b1) {
    __shared__ float sA[64 * 64];
    __shared__ float sB[64 * 64];
    int tid = threadIdx.x;
    for (int idx = tid; idx < 4096; idx += blockDim.x) {
        int k = idx >> 6, j = idx & 63;
        int si = k * 64 + ((j & 31) << 1) + (j >> 5);   // float2-interleaved (j, j+32)
        sA[si] = W1[k * HD + j];
        sB[si] = W1[(64 + k) * HD + j];
    }
    __syncthreads();
    int lane = tid & 31, wid = tid >> 5;
    int nwarp = (blockDim.x >> 5) * gridDim.x;
    const float2* A2 = (const float2*)sA;
    const float2* B2 = (const float2*)sB;
    for (int n = blockIdx.x * (blockDim.x >> 5) + wid; n < NND; n += nwarp) {
        float hl = h[n * HD + lane];
        float hh = h[n * HD + 32 + lane];
        float a0 = b1[lane], a1 = b1[32 + lane];
        float p0 = 0.f, p1 = 0.f;
#pragma unroll
        for (int k = 0; k < 32; k++) {
            float v = __shfl_sync(0xffffffffu, hl, k);
            float2 wa = A2[k * 32 + lane];
            float2 wb = B2[k * 32 + lane];
            a0 += v * wa.x; a1 += v * wa.y;
            p0 += v * wb.x; p1 += v * wb.y;
        }
#pragma unroll
        for (int k = 0; k < 32; k++) {
            float v = __shfl_sync(0xffffffffu, hh, k);
            float2 wa = A2[(32 + k) * 32 + lane];
            float2 wb = B2[(32 + k) * 32 + lane];
            a0 += v * wa.x; a1 += v * wa.y;
            p0 += v * wb.x; p1 += v * wb.y;
        }
        g_PA[n * HD + lane] = a0;  g_PA[n * HD + 32 + lane] = a1;
        g_PB[n * HD + lane] = p0;  g_PB[n * HD + 32 + lane] = p1;
        g_agg[n * HD + lane] = 0.f; g_agg[n * HD + 32 + lane] = 0.f;
    }
}

// ---------------- edge kernel: v = silu(PA[r]+PB[c]+rad*w1c); u = silu(v@W2+b2)*mask; agg[r]+=u ----------------
__global__ void k_edge(const int* __restrict__ edges,
                       const float* __restrict__ emask,
                       const float* __restrict__ W2,
                       const float* __restrict__ b2,
                       const float* __restrict__ w1c) {
    __shared__ float sW2[64 * 64];
    __shared__ float sC[64];
    __shared__ float sB[64];
    int tid = threadIdx.x;
    for (int idx = tid; idx < 4096; idx += blockDim.x) {
        int k = idx >> 6, j = idx & 63;
        sW2[k * 64 + ((j & 31) << 1) + (j >> 5)] = W2[k * HD + j];
    }
    if (tid < 64) { sC[tid] = w1c[tid]; sB[tid] = b2[tid]; }
    __syncthreads();
    int lane = tid & 31, wid = tid >> 5;
    int nwarp = (blockDim.x >> 5) * gridDim.x;
    const float2* W = (const float2*)sW2;
    float c0 = sC[lane], c1 = sC[32 + lane];
    float bb0 = sB[lane], bb1 = sB[32 + lane];
    for (int t = blockIdx.x * (blockDim.x >> 5) + wid; t < NE / 2; t += nwarp) {
        int e0 = 2 * t, e1 = 2 * t + 1;
        int r0 = edges[e0], cn0 = edges[NE + e0];
        int r1 = edges[e1], cn1 = edges[NE + e1];
        float rad0 = g_radial[e0], rad1 = g_radial[e1];
        float m0 = emask[e0], m1 = emask[e1];
        float va0 = silu(g_PA[r0 * HD + lane]      + g_PB[cn0 * HD + lane]      + rad0 * c0);
        float va1 = silu(g_PA[r0 * HD + 32 + lane] + g_PB[cn0 * HD + 32 + lane] + rad0 * c1);
        float vb0 = silu(g_PA[r1 * HD + lane]      + g_PB[cn1 * HD + lane]      + rad1 * c0);
        float vb1 = silu(g_PA[r1 * HD + 32 + lane] + g_PB[cn1 * HD + 32 + lane] + rad1 * c1);
        float ua0 = bb0, ua1 = bb1, ub0 = bb0, ub1 = bb1;
#pragma unroll
        for (int k = 0; k < 32; k++) {
            float2 w = W[k * 32 + lane];
            float x = __shfl_sync(0xffffffffu, va0, k);
            float y = __shfl_sync(0xffffffffu, vb0, k);
            ua0 += x * w.x; ua1 += x * w.y;
            ub0 += y * w.x; ub1 += y * w.y;
        }
#pragma unroll
        for (int k = 0; k < 32; k++) {
            float2 w = W[(32 + k) * 32 + lane];
            float x = __shfl_sync(0xffffffffu, va1, k);
            float y = __shfl_sync(0xffffffffu, vb1, k);
            ua0 += x * w.x; ua1 += x * w.y;
            ub0 += y * w.x; ub1 += y * w.y;
        }
        ua0 = silu(ua0) * m0; ua1 = silu(ua1) * m0;
        ub0 = silu(ub0) * m1; ub1 = silu(ub1) * m1;
        atomicAdd(&g_agg[r0 * HD + lane],      ua0);
        atomicAdd(&g_agg[r0 * HD + 32 + lane], ua1);
        atomicAdd(&g_agg[r1 * HD + lane],      ub0);
        atomicAdd(&g_agg[r1 * HD + 32 + lane], ub1);
    }
}

// ---------------- node kernel: h' = silu([h,agg,h0]@W1 + b1) @ W2 + b2 ----------------
#define NODE_SMEM_FLOATS (4096 * 3 + 11 * 64 + 64 + 64)
__global__ void k_node(const float* __restrict__ h,
                       const float* __restrict__ h0in,
                       const float* __restrict__ W1,
                       const float* __restrict__ b1,
                       const float* __restrict__ W2,
                       const float* __restrict__ b2,
                       float* __restrict__ hout) {
    extern __shared__ float sm[];
    float* sH  = sm;
    float* sAg = sm + 4096;
    float* sF  = sm + 8192;
    float* sW2 = sm + 8192 + 704;
    float* sB1 = sW2 + 4096;
    float* sB2 = sB1 + 64;
    int tid = threadIdx.x;
    for (int idx = tid; idx < 4096; idx += blockDim.x) {
        int k = idx >> 6, j = idx & 63;
        int si = k * 64 + ((j & 31) << 1) + (j >> 5);
        sH[si]  = W1[k * HD + j];
        sAg[si] = W1[(64 + k) * HD + j];
        sW2[si] = W2[k * HD + j];
    }
    for (int idx = tid; idx < FIN * 64; idx += blockDim.x) {
        int k = idx >> 6, j = idx & 63;
        sF[k * 64 + ((j & 31) << 1) + (j >> 5)] = W1[(128 + k) * HD + j];
    }
    if (tid < 64) { sB1[tid] = b1[tid]; sB2[tid] = b2[tid]; }
    __syncthreads();
    int lane = tid & 31, wid = tid >> 5;
    int nwarp = (blockDim.x >> 5) * gridDim.x;
    const float2* H2 = (const float2*)sH;
    const float2* A2 = (const float2*)sAg;
    const float2* F2 = (const float2*)sF;
    const float2* W22 = (const float2*)sW2;
    for (int n = blockIdx.x * (blockDim.x >> 5) + wid; n < NND; n += nwarp) {
        float hl = h[n * HD + lane],      hh = h[n * HD + 32 + lane];
        float al = g_agg[n * HD + lane],  ah = g_agg[n * HD + 32 + lane];
        float t0 = sB1[lane], t1 = sB1[32 + lane];
#pragma unroll
        for (int k = 0; k < 32; k++) {
            float v = __shfl_sync(0xffffffffu, hl, k);
            float2 w = H2[k * 32 + lane];
            t0 += v * w.x; t1 += v * w.y;
            float u = __shfl_sync(0xffffffffu, al, k);
            float2 w2 = A2[k * 32 + lane];
            t0 += u * w2.x; t1 += u * w2.y;
        }
#pragma unroll
        for (int k = 0; k < 32; k++) {
            float v = __shfl_sync(0xffffffffu, hh, k);
            float2 w = H2[(32 + k) * 32 + lane];
            t0 += v * w.x; t1 += v * w.y;
            float u = __shfl_sync(0xffffffffu, ah, k);
            float2 w2 = A2[(32 + k) * 32 + lane];
            t0 += u * w2.x; t1 += u * w2.y;
        }
#pragma unroll
        for (int f = 0; f < FIN; f++) {
            float v = h0in[n * FIN + f];
            float2 w = F2[f * 32 + lane];
            t0 += v * w.x; t1 += v * w.y;
        }
        t0 = silu(t0); t1 = silu(t1);
        float o0 = sB2[lane], o1 = sB2[32 + lane];
#pragma unroll
        for (int k = 0; k < 32; k++) {
            float v = __shfl_sync(0xffffffffu, t0, k);
            float2 w = W22[k * 32 + lane];
            o0 += v * w.x; o1 += v * w.y;
        }
#pragma unroll
        for (int k = 0; k < 32; k++) {
            float v = __shfl_sync(0xffffffffu, t1, k);
            float2 w = W22[(32 + k) * 32 + lane];
            o0 += v * w.x; o1 += v * w.y;
        }
        hout[n * HD + lane] = o0;
        hout[n * HD + 32 + lane] = o1;
    }
}

// ---------------- zero output ----------------
__global__ void k_zero(float* __restrict__ pred) {
    pred[blockIdx.x * blockDim.x + threadIdx.x] = 0.f;
}

// ---------------- final: decoder + pool + graph decoder + signed scatter ----------------
#define FINAL_SMEM_FLOATS (4096 * 3 + 64 * 3 + 256)
__global__ void k_final(const float* __restrict__ h,
                        const float* __restrict__ nmask,
                        const float* __restrict__ dw1, const float* __restrict__ db1,
                        const float* __restrict__ dw2, const float* __restrict__ db2,
                        const float* __restrict__ gw1, const float* __restrict__ gb1,
                        const float* __restrict__ gw2, const float* __restrict__ gb2,
                        const int* __restrict__ ridx, const float* __restrict__ rsign,
                        float* __restrict__ pred) {
    extern __shared__ float sm[];
    float* sD1 = sm;
    float* sD2 = sm + 4096;
    float* sG1 = sm + 8192;
    float* sDB1 = sm + 12288;
    float* sDB2 = sDB1 + 64;
    float* sGB1 = sDB2 + 64;
    float* red  = sGB1 + 64;   // 4*64
    int tid = threadIdx.x;     // 128 threads
    for (int idx = tid; idx < 4096; idx += blockDim.x) {
        int k = idx >> 6, j = idx & 63;
        int si = k * 64 + ((j & 31) << 1) + (j >> 5);
        sD1[si] = dw1[k * HD + j];
        sD2[si] = dw2[k * HD + j];
        sG1[si] = gw1[k * HD + j];
    }
    if (tid < 64) { sDB1[tid] = db1[tid]; sDB2[tid] = db2[tid]; sGB1[tid] = gb1[tid]; }
    __syncthreads();
    int lane = tid & 31, wid = tid >> 5;
    int g = blockIdx.x;
    const float2* D1 = (const float2*)sD1;
    const float2* D2 = (const float2*)sD2;
    const float2* G1 = (const float2*)sG1;
    float acc0 = 0.f, acc1 = 0.f;
#pragma unroll
    for (int i = 0; i < 4; i++) {
        int n = g * NPG + wid * 4 + i;
        float hl = h[n * HD + lane], hh = h[n * HD + 32 + lane];
        float t0 = sDB1[lane], t1 = sDB1[32 + lane];
#pragma unroll
        for (int k = 0; k < 32; k++) {
            float v = __shfl_sync(0xffffffffu, hl, k);
            float2 w = D1[k * 32 + lane];
            t0 += v * w.x; t1 += v * w.y;
        }
#pragma unroll
        for (int k = 0; k < 32; k++) {
            float v = __shfl_sync(0xffffffffu, hh, k);
            float2 w = D1[(32 + k) * 32 + lane];
            t0 += v * w.x; t1 += v * w.y;
        }
        t0 = silu(t0); t1 = silu(t1);
        float o0 = sDB2[lane], o1 = sDB2[32 + lane];
#pragma unroll
        for (int k = 0; k < 32; k++) {
            float v = __shfl_sync(0xffffffffu, t0, k);
            float2 w = D2[k * 32 + lane];
            o0 += v * w.x; o1 += v * w.y;
        }
#pragma unroll
        for (int k = 0; k < 32; k++) {
            float v = __shfl_sync(0xffffffffu, t1, k);
            float2 w = D2[(32 + k) * 32 + lane];
            o0 += v * w.x; o1 += v * w.y;
        }
        float m = nmask[n];
        acc0 += o0 * m; acc1 += o1 * m;
    }
    red[wid * 64 + lane] = acc0;
    red[wid * 64 + 32 + lane] = acc1;
    __syncthreads();
    if (wid == 0) {
        float hg0 = red[lane] + red[64 + lane] + red[128 + lane] + red[192 + lane];
        float hg1 = red[32 + lane] + red[96 + lane] + red[160 + lane] + red[224 + lane];
        float t0 = sGB1[lane], t1 = sGB1[32 + lane];
#pragma unroll
        for (int k = 0; k < 32; k++) {
            float v = __shfl_sync(0xffffffffu, hg0, k);
            float2 w = G1[k * 32 + lane];
            t0 += v * w.x; t1 += v * w.y;
        }
#pragma unroll
        for (int k = 0; k < 32; k++) {
            float v = __shfl_sync(0xffffffffu, hg1, k);
            float2 w = G1[(32 + k) * 32 + lane];
            t0 += v * w.x; t1 += v * w.y;
        }
        t0 = silu(t0); t1 = silu(t1);
        float part = t0 * gw2[lane] + t1 * gw2[32 + lane];
#pragma unroll
        for (int off = 16; off > 0; off >>= 1)
            part += __shfl_xor_sync(0xffffffffu, part, off);
        if (lane == 0) {
            float val = (part + gb2[0]) * rsign[g];
            atomicAdd(&pred[ridx[g]], val);
        }
    }
}

// ---------------- launch ----------------
extern "C" void kernel_launch(void* const* d_in, const int* in_sizes, int n_in,
                              void* d_out, int out_size) {
    const float* h0    = (const float*)d_in[0];
    const float* pos   = (const float*)d_in[1];
    const int*   edges = (const int*)  d_in[2];
    const float* nmask = (const float*)d_in[3];
    const float* emask = (const float*)d_in[4];
    const int*   ridx  = (const int*)  d_in[5];
    const float* rsign = (const float*)d_in[6];
    const float* emb_w = (const float*)d_in[7];
    const float* emb_b = (const float*)d_in[8];
    const float* ew1   = (const float*)d_in[9];
    const float* eb1   = (const float*)d_in[10];
    const float* ew2   = (const float*)d_in[11];
    const float* eb2   = (const float*)d_in[12];
    const float* nw1   = (const float*)d_in[13];
    const float* nb1   = (const float*)d_in[14];
    const float* nw2   = (const float*)d_in[15];
    const float* nb2   = (const float*)d_in[16];
    const float* dw1   = (const float*)d_in[17];
    const float* db1   = (const float*)d_in[18];
    const float* dw2   = (const float*)d_in[19];
    const float* db2   = (const float*)d_in[20];
    const float* gw1   = (const float*)d_in[21];
    const float* gb1   = (const float*)d_in[22];
    const float* gw2   = (const float*)d_in[23];
    const float* gb2   = (const float*)d_in[24];
    float* pred = (float*)d_out;

    float *hA, *hB;
    cudaGetSymbolAddress((void**)&hA, g_h);
    cudaGetSymbolAddress((void**)&hB, g_h2);

    cudaFuncSetAttribute(k_node, cudaFuncAttributeMaxDynamicSharedMemorySize,
                         NODE_SMEM_FLOATS * 4);
    cudaFuncSetAttribute(k_final, cudaFuncAttributeMaxDynamicSharedMemorySize,
                         FINAL_SMEM_FLOATS * 4);

    k_embed<<<NND * HD / 256, 256>>>(h0, emb_w, emb_b);
    k_radial<<<(NE + 255) / 256, 256>>>(edges, pos);

    float* hc = hA;
    float* hn = hB;
    for (int l = 0; l < NL; l++) {
        k_precomp<<<1024, 256>>>(hc, ew1 + l * EINC * HD, eb1 + l * HD);
        k_edge<<<2048, 256>>>(edges, emask, ew2 + l * HD * HD, eb2 + l * HD,
                              ew1 + l * EINC * HD + 128 * HD);
        k_node<<<1024, 256, NODE_SMEM_FLOATS * 4>>>(
            hc, h0, nw1 + l * NINC * HD, nb1 + l * HD,
            nw2 + l * HD * HD, nb2 + l * HD, hn);
        float* t = hc; hc = hn; hn = t;
    }

    k_zero<<<NR / 256, 256>>>(pred);
    k_final<<<NG, 128, FINAL_SMEM_FLOATS * 4>>>(
        hc, nmask, dw1, db1, dw2, db2, gw1, gb1, gw2, gb2, ridx, rsign, pred);
}